// round 2
// baseline (speedup 1.0000x reference)
#include <cuda_runtime.h>
#include <math.h>

#define NN 6000
#define EE 100000

// ---------------- device scratch (static, no allocation) ----------------
__device__ int g_deg[NN];
__device__ int g_rowptr[NN + 1];
__device__ int g_cursor[NN];
__device__ int g_eidx[EE];

__device__ __align__(16) float g_W0[2 * NN * 32];   // layer-0 relation weights (embedding)
__device__ __align__(16) float g_Wl[2 * 64 * 64];   // per-layer combined relation weights
__device__ __align__(16) float g_xA[NN * 64];
__device__ __align__(16) float g_xB[NN * 64];
__device__ __align__(16) float g_hr[2 * NN * 64];   // per-relation transformed features
__device__ __align__(16) float g_rootout[NN * 64];

__device__ __align__(16) float g_h[NN * 512];       // GAT hidden
__device__ float g_asv[NN], g_adv[NN], g_amax[NN], g_denom[NN];
__device__ float g_ex[EE];
__device__ __align__(16) float g_gat[NN * 512];     // GAT output (relu'd)
__device__ __align__(16) float g_pt[NN * 128];      // x @ w1[0:512]   (+ b1)
__device__ __align__(16) float g_pb[NN * 128];      // x @ w1[512:1024]

// ---------------- helpers ----------------
__device__ __forceinline__ float lrelu(float v) { return v > 0.f ? v : 0.2f * v; }

__device__ __forceinline__ void atomicMaxFloat(float* addr, float val) {
    int* ai = (int*)addr;
    int old = *ai;
    while (__int_as_float(old) < val) {
        int assumed = old;
        old = atomicCAS(ai, assumed, __float_as_int(val));
        if (old == assumed) break;
    }
}

// ---------------- CSR build ----------------
__global__ void zero_deg_kernel() {
    int i = blockIdx.x * blockDim.x + threadIdx.x;
    if (i < NN) g_deg[i] = 0;
}

__global__ void count_kernel(const int* __restrict__ dst) {
    int e = blockIdx.x * blockDim.x + threadIdx.x;
    if (e < EE) atomicAdd(&g_deg[dst[e]], 1);
}

// single-block exclusive scan of g_deg -> g_rowptr, also sets g_cursor
__global__ void scan_kernel() {
    __shared__ int sh[1024];
    __shared__ int carry;
    int tid = threadIdx.x;
    if (tid == 0) { carry = 0; g_rowptr[0] = 0; }
    __syncthreads();
    for (int base = 0; base < NN; base += 1024) {
        int i = base + tid;
        int v = (i < NN) ? g_deg[i] : 0;
        sh[tid] = v;
        __syncthreads();
        for (int off = 1; off < 1024; off <<= 1) {
            int t = (tid >= off) ? sh[tid - off] : 0;
            __syncthreads();
            sh[tid] += t;
            __syncthreads();
        }
        int incl = carry + sh[tid];
        if (i < NN) { g_rowptr[i + 1] = incl; g_cursor[i] = incl - v; }
        __syncthreads();
        if (tid == 0) carry += sh[1023];
        __syncthreads();
    }
}

__global__ void scatter_kernel(const int* __restrict__ dst) {
    int e = blockIdx.x * blockDim.x + threadIdx.x;
    if (e < EE) {
        int p = atomicAdd(&g_cursor[dst[e]], 1);
        g_eidx[p] = e;
    }
}

// ---------------- RGCN layer 0 (input = identity => pure lookup) ----------------
__global__ void w0_kernel(const float* __restrict__ basis0, const float* __restrict__ comp0) {
    int idx = blockIdx.x * blockDim.x + threadIdx.x;
    if (idx >= 2 * NN * 32) return;
    int r = idx / (NN * 32);
    int rem = idx - r * NN * 32;
    float v = 0.f;
#pragma unroll
    for (int b = 0; b < 4; b++) v += comp0[r * 4 + b] * basis0[b * NN * 32 + rem];
    g_W0[idx] = v;
}

__global__ void l0_agg_kernel(const int* __restrict__ src, const int* __restrict__ et,
                              const float* __restrict__ root0, const float* __restrict__ rbias0) {
    int warp = (blockIdx.x * blockDim.x + threadIdx.x) >> 5;
    int lane = threadIdx.x & 31;
    if (warp >= NN) return;
    int beg = g_rowptr[warp], end = g_rowptr[warp + 1];
    float a0 = 0.f, a1 = 0.f, c0 = 0.f, c1 = 0.f;
    for (int k = beg; k < end; k++) {
        int e = g_eidx[k];
        int s = src[e];
        int t = et[e];
        float v = g_W0[t * (NN * 32) + s * 32 + lane];
        if (t == 0) { a0 += v; c0 += 1.f; } else { a1 += v; c1 += 1.f; }
    }
    float out = root0[warp * 32 + lane] + rbias0[lane]
              + a0 / fmaxf(c0, 1.f) + a1 / fmaxf(c1, 1.f);
    g_xA[warp * 32 + lane] = tanhf(out);
}

// ---------------- RGCN layers 1..3 ----------------
__global__ void wl_kernel(const float* __restrict__ basis, const float* __restrict__ comp,
                          int din, int dout) {
    int idx = blockIdx.x * blockDim.x + threadIdx.x;
    int per = din * dout;
    if (idx >= 2 * per) return;
    int r = idx / per;
    int rem = idx - r * per;
    float v = 0.f;
#pragma unroll
    for (int b = 0; b < 4; b++) v += comp[r * 4 + b] * basis[b * per + rem];
    g_Wl[idx] = v;
}

template <int DIN, int DOUT>
__global__ void dense_kernel(const float* __restrict__ root, const float* __restrict__ rbias,
                             int in_sel) {
    const float* xin = in_sel ? g_xB : g_xA;
    constexpr int NPB = 256 / DOUT;
    __shared__ float sx[NPB][DIN];
    int tid = threadIdx.x;
    int node0 = blockIdx.x * NPB;
    for (int i = tid; i < NPB * DIN; i += 256) {
        int nn = node0 + i / DIN;
        sx[i / DIN][i % DIN] = (nn < NN) ? xin[nn * DIN + (i % DIN)] : 0.f;
    }
    __syncthreads();
    int ln = tid / DOUT, o = tid % DOUT;
    int node = node0 + ln;
    if (node >= NN) return;
    float a0 = 0.f, a1 = 0.f, ar = 0.f;
#pragma unroll 8
    for (int i = 0; i < DIN; i++) {
        float xv = sx[ln][i];
        a0 += xv * g_Wl[i * DOUT + o];
        a1 += xv * g_Wl[DIN * DOUT + i * DOUT + o];
        ar += xv * root[i * DOUT + o];
    }
    g_hr[node * DOUT + o] = a0;
    g_hr[NN * DOUT + node * DOUT + o] = a1;
    g_rootout[node * DOUT + o] = ar + rbias[o];
}

template <int DOUT>
__global__ void agg_kernel(const int* __restrict__ src, const int* __restrict__ et, int out_sel) {
    float* xout = out_sel ? g_xB : g_xA;
    constexpr int NPB = 256 / DOUT;
    int tid = threadIdx.x;
    int ln = tid / DOUT, o = tid % DOUT;
    int node = blockIdx.x * NPB + ln;
    if (node >= NN) return;
    int beg = g_rowptr[node], end = g_rowptr[node + 1];
    float a0 = 0.f, a1 = 0.f, c0 = 0.f, c1 = 0.f;
    for (int k = beg; k < end; k++) {
        int e = g_eidx[k];
        int s = src[e];
        int t = et[e];
        float v = g_hr[t * (NN * DOUT) + s * DOUT + o];
        if (t == 0) { a0 += v; c0 += 1.f; } else { a1 += v; c1 += 1.f; }
    }
    float out = g_rootout[node * DOUT + o] + a0 / fmaxf(c0, 1.f) + a1 / fmaxf(c1, 1.f);
    xout[node * DOUT + o] = tanhf(out);
}

// ---------------- GAT ----------------
__global__ void gat_h_kernel(const float* __restrict__ gw) {
    __shared__ float sx[8][32];
    int tid = threadIdx.x;  // 512
    int node0 = blockIdx.x * 8;
    for (int i = tid; i < 8 * 32; i += 512) {
        int nn = node0 + (i >> 5);
        sx[i >> 5][i & 31] = (nn < NN) ? g_xB[nn * 32 + (i & 31)] : 0.f;
    }
    __syncthreads();
    float acc[8] = {0.f, 0.f, 0.f, 0.f, 0.f, 0.f, 0.f, 0.f};
    for (int i = 0; i < 32; i++) {
        float wv = gw[i * 512 + tid];
#pragma unroll
        for (int t = 0; t < 8; t++) acc[t] += sx[t][i] * wv;
    }
#pragma unroll
    for (int t = 0; t < 8; t++) {
        int nn = node0 + t;
        if (nn < NN) g_h[nn * 512 + tid] = acc[t];
    }
}

__global__ void asvadv_kernel(const float* __restrict__ as, const float* __restrict__ ad) {
    int warp = (blockIdx.x * blockDim.x + threadIdx.x) >> 5;
    int lane = threadIdx.x & 31;
    if (warp >= NN) return;
    float s = 0.f, d = 0.f;
    for (int j = lane; j < 512; j += 32) {
        float hv = g_h[warp * 512 + j];
        s += hv * as[j];
        d += hv * ad[j];
    }
#pragma unroll
    for (int off = 16; off; off >>= 1) {
        s += __shfl_down_sync(0xffffffffu, s, off);
        d += __shfl_down_sync(0xffffffffu, d, off);
    }
    if (lane == 0) { g_asv[warp] = s; g_adv[warp] = d; }
}

__global__ void gat_init_kernel() {
    int n = blockIdx.x * blockDim.x + threadIdx.x;
    if (n < NN) g_amax[n] = lrelu(g_asv[n] + g_adv[n]);  // self-loop alpha (no -inf case)
}

__global__ void gat_edge_max_kernel(const int* __restrict__ src, const int* __restrict__ dst) {
    int e = blockIdx.x * blockDim.x + threadIdx.x;
    if (e >= EE) return;
    float a = lrelu(g_asv[src[e]] + g_adv[dst[e]]);
    atomicMaxFloat(&g_amax[dst[e]], a);
}

__global__ void gat_self_ex_kernel() {
    int n = blockIdx.x * blockDim.x + threadIdx.x;
    if (n < NN) {
        float a = lrelu(g_asv[n] + g_adv[n]);
        g_denom[n] = expf(a - g_amax[n]);
    }
}

__global__ void gat_edge_ex_kernel(const int* __restrict__ src, const int* __restrict__ dst) {
    int e = blockIdx.x * blockDim.x + threadIdx.x;
    if (e >= EE) return;
    int s = src[e], d = dst[e];
    float a = lrelu(g_asv[s] + g_adv[d]);
    float ex = expf(a - g_amax[d]);
    g_ex[e] = ex;
    atomicAdd(&g_denom[d], ex);
}

__global__ void gat_agg_kernel(const int* __restrict__ src, const float* __restrict__ gbias) {
    __shared__ float sex[64];
    __shared__ int ssrc[64];
    int n = blockIdx.x, o = threadIdx.x;  // 512 threads
    int beg = g_rowptr[n];
    int deg = g_rowptr[n + 1] - beg;
    float aself = lrelu(g_asv[n] + g_adv[n]);
    float exself = expf(aself - g_amax[n]);
    float acc = exself * g_h[n * 512 + o];
    for (int base = 0; base < deg; base += 64) {
        int cnt = min(64, deg - base);
        if (o < cnt) {
            int e = g_eidx[beg + base + o];
            sex[o] = g_ex[e];
            ssrc[o] = src[e];
        }
        __syncthreads();
        for (int j = 0; j < cnt; j++) acc += sex[j] * g_h[ssrc[j] * 512 + o];
        __syncthreads();
    }
    float out = acc / fmaxf(g_denom[n], 1e-16f) + gbias[o];
    g_gat[n * 512 + o] = fmaxf(out, 0.f);
}

// ---------------- edge MLP: factored through per-node projections ----------------
__global__ void ptpb_kernel(const float* __restrict__ w1, const float* __restrict__ b1) {
    __shared__ float sx[8][512];
    int tid = threadIdx.x;  // 128
    int node0 = blockIdx.x * 8;
    for (int i = tid; i < 8 * 512; i += 128) {
        int nn = node0 + (i >> 9);
        sx[i >> 9][i & 511] = (nn < NN) ? g_gat[nn * 512 + (i & 511)] : 0.f;
    }
    __syncthreads();
    float at[8] = {0.f, 0.f, 0.f, 0.f, 0.f, 0.f, 0.f, 0.f};
    float ab[8] = {0.f, 0.f, 0.f, 0.f, 0.f, 0.f, 0.f, 0.f};
    for (int i = 0; i < 512; i++) {
        float wt = w1[i * 128 + tid];
        float wb = w1[(512 + i) * 128 + tid];
#pragma unroll
        for (int t = 0; t < 8; t++) {
            float xv = sx[t][i];
            at[t] += xv * wt;
            ab[t] += xv * wb;
        }
    }
    float bb = b1[tid];
#pragma unroll
    for (int t = 0; t < 8; t++) {
        int nn = node0 + t;
        if (nn < NN) {
            g_pt[nn * 128 + tid] = at[t] + bb;
            g_pb[nn * 128 + tid] = ab[t];
        }
    }
}

__global__ void edge_out_kernel(const int* __restrict__ src, const int* __restrict__ dst,
                                const float* __restrict__ w2, const float* __restrict__ b2,
                                float* __restrict__ out) {
    int warp = (blockIdx.x * blockDim.x + threadIdx.x) >> 5;
    int lane = threadIdx.x & 31;
    if (warp >= EE) return;
    const float4* pt4 = (const float4*)(g_pt + (size_t)src[warp] * 128);
    const float4* pb4 = (const float4*)(g_pb + (size_t)dst[warp] * 128);
    const float4* w4 = (const float4*)w2;
    float4 a = pt4[lane], b = pb4[lane], w = w4[lane];
    float acc = fmaxf(a.x + b.x, 0.f) * w.x + fmaxf(a.y + b.y, 0.f) * w.y
              + fmaxf(a.z + b.z, 0.f) * w.z + fmaxf(a.w + b.w, 0.f) * w.w;
#pragma unroll
    for (int off = 16; off; off >>= 1) acc += __shfl_down_sync(0xffffffffu, acc, off);
    if (lane == 0) {
        float z = acc + b2[0];
        out[warp] = 1.f / (1.f + expf(-z));
    }
}

// ---------------- launch ----------------
extern "C" void kernel_launch(void* const* d_in, const int* in_sizes, int n_in,
                              void* d_out, int out_size) {
    // Two possible orderings: signature order (edge_index first, 2E=200000 ints)
    // or setup_inputs dict order (basis0 first, 768000 floats).
    int off, iE, iT;
    if (in_sizes[0] == 2 * EE) { off = 2; iE = 0; iT = 1; }
    else                       { off = 0; iE = 24; iT = 25; }
    const int* ei = (const int*)d_in[iE];
    const int* et = (const int*)d_in[iT];
    const int* src = ei;
    const int* dst = ei + EE;
    const float* basis0 = (const float*)d_in[off + 0];
    const float* comp0  = (const float*)d_in[off + 1];
    const float* root0  = (const float*)d_in[off + 2];
    const float* rbias0 = (const float*)d_in[off + 3];
    const float* basis1 = (const float*)d_in[off + 4];
    const float* comp1  = (const float*)d_in[off + 5];
    const float* root1  = (const float*)d_in[off + 6];
    const float* rbias1 = (const float*)d_in[off + 7];
    const float* basis2 = (const float*)d_in[off + 8];
    const float* comp2  = (const float*)d_in[off + 9];
    const float* root2  = (const float*)d_in[off + 10];
    const float* rbias2 = (const float*)d_in[off + 11];
    const float* basis3 = (const float*)d_in[off + 12];
    const float* comp3  = (const float*)d_in[off + 13];
    const float* root3  = (const float*)d_in[off + 14];
    const float* rbias3 = (const float*)d_in[off + 15];
    const float* gw  = (const float*)d_in[off + 16];
    const float* gas = (const float*)d_in[off + 17];
    const float* gad = (const float*)d_in[off + 18];
    const float* gb  = (const float*)d_in[off + 19];
    const float* w1  = (const float*)d_in[off + 20];
    const float* b1  = (const float*)d_in[off + 21];
    const float* w2  = (const float*)d_in[off + 22];
    const float* b2  = (const float*)d_in[off + 23];
    float* out = (float*)d_out;

    // CSR build (by dst)
    zero_deg_kernel<<<(NN + 255) / 256, 256>>>();
    count_kernel<<<(EE + 255) / 256, 256>>>(dst);
    scan_kernel<<<1, 1024>>>();
    scatter_kernel<<<(EE + 255) / 256, 256>>>(dst);

    // layer 0 (identity input => lookup)
    w0_kernel<<<(2 * NN * 32 + 255) / 256, 256>>>(basis0, comp0);
    l0_agg_kernel<<<(NN * 32 + 255) / 256, 256>>>(src, et, root0, rbias0);

    // layer 1: 32 -> 64  (xA -> xB)
    wl_kernel<<<(2 * 32 * 64 + 255) / 256, 256>>>(basis1, comp1, 32, 64);
    dense_kernel<32, 64><<<(NN + 3) / 4, 256>>>(root1, rbias1, 0);
    agg_kernel<64><<<(NN + 3) / 4, 256>>>(src, et, 1);

    // layer 2: 64 -> 64  (xB -> xA)
    wl_kernel<<<(2 * 64 * 64 + 255) / 256, 256>>>(basis2, comp2, 64, 64);
    dense_kernel<64, 64><<<(NN + 3) / 4, 256>>>(root2, rbias2, 1);
    agg_kernel<64><<<(NN + 3) / 4, 256>>>(src, et, 0);

    // layer 3: 64 -> 32  (xA -> xB)
    wl_kernel<<<(2 * 64 * 32 + 255) / 256, 256>>>(basis3, comp3, 64, 32);
    dense_kernel<64, 32><<<(NN + 7) / 8, 256>>>(root3, rbias3, 0);
    agg_kernel<32><<<(NN + 7) / 8, 256>>>(src, et, 1);

    // GAT
    gat_h_kernel<<<(NN + 7) / 8, 512>>>(gw);
    asvadv_kernel<<<(NN * 32 + 255) / 256, 256>>>(gas, gad);
    gat_init_kernel<<<(NN + 255) / 256, 256>>>();
    gat_edge_max_kernel<<<(EE + 255) / 256, 256>>>(src, dst);
    gat_self_ex_kernel<<<(NN + 255) / 256, 256>>>();
    gat_edge_ex_kernel<<<(EE + 255) / 256, 256>>>(src, dst);
    gat_agg_kernel<<<NN, 512>>>(src, gb);

    // edge MLP factored through node projections
    ptpb_kernel<<<(NN + 7) / 8, 128>>>(w1, b1);
    edge_out_kernel<<<(EE * 32 + 255) / 256, 256>>>(src, dst, w2, b2, out);
}

// round 3
// speedup vs baseline: 1.1699x; 1.1699x over previous
#include <cuda_runtime.h>
#include <math.h>

#define NN 6000
#define EE 100000

// ---------------- device scratch (static, no allocation) ----------------
__device__ int g_deg[NN];
__device__ int g_rowptr[NN + 1];
__device__ int g_cursor[NN];
__device__ int g_eidx[EE];

__device__ __align__(16) float g_W0[2 * NN * 32];   // layer-0 relation weights (embedding)
__device__ __align__(16) float g_Wl1[2 * 32 * 64];
__device__ __align__(16) float g_Wl2[2 * 64 * 64];
__device__ __align__(16) float g_Wl3[2 * 64 * 32];
__device__ __align__(16) float g_xA[NN * 64];
__device__ __align__(16) float g_xB[NN * 64];
__device__ __align__(16) float g_hr[2 * NN * 64];   // per-relation transformed features
__device__ __align__(16) float g_rootout[NN * 64];

__device__ __align__(16) float g_h[NN * 512];       // GAT hidden
__device__ float g_asv[NN], g_adv[NN];
__device__ __align__(16) float g_gat[NN * 512];     // GAT output (relu'd)
__device__ __align__(16) float g_pt[NN * 128];      // x @ w1[0:512]   (+ b1)
__device__ __align__(16) float g_pb[NN * 128];      // x @ w1[512:1024]

// ---------------- helpers ----------------
__device__ __forceinline__ float lrelu(float v) { return v > 0.f ? v : 0.2f * v; }

// ---------------- fused precompute: W0, Wl1..3, zero deg ----------------
#define W0_CNT (2 * NN * 32)
#define WL1_CNT (2 * 32 * 64)
#define WL2_CNT (2 * 64 * 64)
#define WL3_CNT (2 * 64 * 32)
#define PRE_TOTAL (W0_CNT + WL1_CNT + WL2_CNT + WL3_CNT + NN)

__global__ void precompute_kernel(const float* __restrict__ basis0, const float* __restrict__ comp0,
                                  const float* __restrict__ basis1, const float* __restrict__ comp1,
                                  const float* __restrict__ basis2, const float* __restrict__ comp2,
                                  const float* __restrict__ basis3, const float* __restrict__ comp3) {
    int idx = blockIdx.x * blockDim.x + threadIdx.x;
    if (idx < W0_CNT) {
        int per = NN * 32;
        int r = idx / per, rem = idx - r * per;
        float v = 0.f;
#pragma unroll
        for (int b = 0; b < 4; b++) v += comp0[r * 4 + b] * basis0[b * per + rem];
        g_W0[idx] = v;
        return;
    }
    idx -= W0_CNT;
    if (idx < WL1_CNT) {
        int per = 32 * 64;
        int r = idx / per, rem = idx - r * per;
        float v = 0.f;
#pragma unroll
        for (int b = 0; b < 4; b++) v += comp1[r * 4 + b] * basis1[b * per + rem];
        g_Wl1[idx] = v;
        return;
    }
    idx -= WL1_CNT;
    if (idx < WL2_CNT) {
        int per = 64 * 64;
        int r = idx / per, rem = idx - r * per;
        float v = 0.f;
#pragma unroll
        for (int b = 0; b < 4; b++) v += comp2[r * 4 + b] * basis2[b * per + rem];
        g_Wl2[idx] = v;
        return;
    }
    idx -= WL2_CNT;
    if (idx < WL3_CNT) {
        int per = 64 * 32;
        int r = idx / per, rem = idx - r * per;
        float v = 0.f;
#pragma unroll
        for (int b = 0; b < 4; b++) v += comp3[r * 4 + b] * basis3[b * per + rem];
        g_Wl3[idx] = v;
        return;
    }
    idx -= WL3_CNT;
    if (idx < NN) g_deg[idx] = 0;
}

// ---------------- CSR build ----------------
__global__ void count_kernel(const int* __restrict__ dst) {
    int e = blockIdx.x * blockDim.x + threadIdx.x;
    if (e < EE) atomicAdd(&g_deg[dst[e]], 1);
}

// single-block exclusive scan of g_deg -> g_rowptr, also sets g_cursor
__global__ void scan_kernel() {
    __shared__ int swsum[32];
    __shared__ int carry;
    int tid = threadIdx.x, lane = tid & 31, wid = tid >> 5;
    if (tid == 0) { carry = 0; g_rowptr[0] = 0; }
    __syncthreads();
    for (int base = 0; base < NN; base += 1024) {
        int i = base + tid;
        int v = (i < NN) ? g_deg[i] : 0;
        int x = v;
#pragma unroll
        for (int off = 1; off < 32; off <<= 1) {
            int t = __shfl_up_sync(0xffffffffu, x, off);
            if (lane >= off) x += t;
        }
        if (lane == 31) swsum[wid] = x;
        __syncthreads();
        if (wid == 0) {
            int y = swsum[lane];
#pragma unroll
            for (int off = 1; off < 32; off <<= 1) {
                int t = __shfl_up_sync(0xffffffffu, y, off);
                if (lane >= off) y += t;
            }
            swsum[lane] = y;
        }
        __syncthreads();
        int incl = x + (wid ? swsum[wid - 1] : 0) + carry;
        if (i < NN) { g_rowptr[i + 1] = incl; g_cursor[i] = incl - v; }
        __syncthreads();
        if (tid == 0) carry += swsum[31];
        __syncthreads();
    }
}

__global__ void scatter_kernel(const int* __restrict__ dst) {
    int e = blockIdx.x * blockDim.x + threadIdx.x;
    if (e < EE) {
        int p = atomicAdd(&g_cursor[dst[e]], 1);
        g_eidx[p] = e;
    }
}

// ---------------- RGCN layer 0 (input = identity => pure lookup) ----------------
__global__ void l0_agg_kernel(const int* __restrict__ src, const int* __restrict__ et,
                              const float* __restrict__ root0, const float* __restrict__ rbias0) {
    int warp = (blockIdx.x * blockDim.x + threadIdx.x) >> 5;
    int lane = threadIdx.x & 31;
    if (warp >= NN) return;
    int beg = g_rowptr[warp], end = g_rowptr[warp + 1];
    float a0 = 0.f, a1 = 0.f, c0 = 0.f, c1 = 0.f;
    for (int k = beg; k < end; k++) {
        int e = g_eidx[k];
        int s = src[e];
        int t = et[e];
        float v = g_W0[t * (NN * 32) + s * 32 + lane];
        if (t == 0) { a0 += v; c0 += 1.f; } else { a1 += v; c1 += 1.f; }
    }
    float out = root0[warp * 32 + lane] + rbias0[lane]
              + a0 / fmaxf(c0, 1.f) + a1 / fmaxf(c1, 1.f);
    g_xA[warp * 32 + lane] = tanhf(out);
}

// ---------------- RGCN layers 1..3 ----------------
template <int DIN, int DOUT>
__global__ void dense_kernel(const float* __restrict__ root, const float* __restrict__ rbias,
                             int in_sel, int layer) {
    const float* xin = in_sel ? g_xB : g_xA;
    const float* W = (layer == 1) ? g_Wl1 : (layer == 2) ? g_Wl2 : g_Wl3;
    constexpr int NPB = 256 / DOUT;
    __shared__ float sx[NPB][DIN];
    int tid = threadIdx.x;
    int node0 = blockIdx.x * NPB;
    for (int i = tid; i < NPB * DIN; i += 256) {
        int nn = node0 + i / DIN;
        sx[i / DIN][i % DIN] = (nn < NN) ? xin[nn * DIN + (i % DIN)] : 0.f;
    }
    __syncthreads();
    int ln = tid / DOUT, o = tid % DOUT;
    int node = node0 + ln;
    if (node >= NN) return;
    float a0 = 0.f, a1 = 0.f, ar = 0.f;
#pragma unroll 8
    for (int i = 0; i < DIN; i++) {
        float xv = sx[ln][i];
        a0 += xv * W[i * DOUT + o];
        a1 += xv * W[DIN * DOUT + i * DOUT + o];
        ar += xv * root[i * DOUT + o];
    }
    g_hr[node * DOUT + o] = a0;
    g_hr[NN * DOUT + node * DOUT + o] = a1;
    g_rootout[node * DOUT + o] = ar + rbias[o];
}

template <int DOUT>
__global__ void agg_kernel(const int* __restrict__ src, const int* __restrict__ et, int out_sel) {
    float* xout = out_sel ? g_xB : g_xA;
    constexpr int NPB = 256 / DOUT;
    int tid = threadIdx.x;
    int ln = tid / DOUT, o = tid % DOUT;
    int node = blockIdx.x * NPB + ln;
    if (node >= NN) return;
    int beg = g_rowptr[node], end = g_rowptr[node + 1];
    float a0 = 0.f, a1 = 0.f, c0 = 0.f, c1 = 0.f;
    for (int k = beg; k < end; k++) {
        int e = g_eidx[k];
        int s = src[e];
        int t = et[e];
        float v = g_hr[t * (NN * DOUT) + s * DOUT + o];
        if (t == 0) { a0 += v; c0 += 1.f; } else { a1 += v; c1 += 1.f; }
    }
    float out = g_rootout[node * DOUT + o] + a0 / fmaxf(c0, 1.f) + a1 / fmaxf(c1, 1.f);
    xout[node * DOUT + o] = tanhf(out);
}

// ---------------- GAT h = x @ gat_w, fused asv/adv reduction ----------------
// 16 nodes/block, 512 threads, thread tile = 4 nodes x 4 cols.
__global__ void gat_h_kernel(const float* __restrict__ gw,
                             const float* __restrict__ as, const float* __restrict__ ad) {
    __shared__ __align__(16) float sx[16][32];
    __shared__ float s_as[16], s_ad[16];
    int tid = threadIdx.x;  // 512
    int node0 = blockIdx.x * 16;
    for (int i = tid; i < 16 * 32; i += 512) {
        int nn = node0 + (i >> 5);
        sx[i >> 5][i & 31] = (nn < NN) ? g_xB[nn * 32 + (i & 31)] : 0.f;
    }
    if (tid < 16) { s_as[tid] = 0.f; s_ad[tid] = 0.f; }
    __syncthreads();
    int cg = tid & 127;        // 128 col groups -> cols 4*cg
    int ng = tid >> 7;         // 4 node groups -> nodes 4*ng..
    int col4 = cg * 4;
    int nbase = ng * 4;
    float acc[4][4];
#pragma unroll
    for (int a = 0; a < 4; a++)
#pragma unroll
        for (int b = 0; b < 4; b++) acc[a][b] = 0.f;
#pragma unroll 8
    for (int i = 0; i < 32; i++) {
        float4 wv = *(const float4*)(gw + i * 512 + col4);
        float x0 = sx[nbase + 0][i], x1 = sx[nbase + 1][i];
        float x2 = sx[nbase + 2][i], x3 = sx[nbase + 3][i];
        acc[0][0] += x0 * wv.x; acc[0][1] += x0 * wv.y; acc[0][2] += x0 * wv.z; acc[0][3] += x0 * wv.w;
        acc[1][0] += x1 * wv.x; acc[1][1] += x1 * wv.y; acc[1][2] += x1 * wv.z; acc[1][3] += x1 * wv.w;
        acc[2][0] += x2 * wv.x; acc[2][1] += x2 * wv.y; acc[2][2] += x2 * wv.z; acc[2][3] += x2 * wv.w;
        acc[3][0] += x3 * wv.x; acc[3][1] += x3 * wv.y; acc[3][2] += x3 * wv.z; acc[3][3] += x3 * wv.w;
    }
    // store h
#pragma unroll
    for (int a = 0; a < 4; a++) {
        int nn = node0 + nbase + a;
        float4 o = make_float4(acc[a][0], acc[a][1], acc[a][2], acc[a][3]);
        *(float4*)(g_h + (size_t)nn * 512 + col4) = o;
    }
    // fused asv/adv: per-node dot with attention vectors
    float4 av = *(const float4*)(as + col4);
    float4 dv = *(const float4*)(ad + col4);
    int lane = tid & 31;
#pragma unroll
    for (int a = 0; a < 4; a++) {
        float ps = acc[a][0] * av.x + acc[a][1] * av.y + acc[a][2] * av.z + acc[a][3] * av.w;
        float pd = acc[a][0] * dv.x + acc[a][1] * dv.y + acc[a][2] * dv.z + acc[a][3] * dv.w;
#pragma unroll
        for (int off = 16; off; off >>= 1) {
            ps += __shfl_down_sync(0xffffffffu, ps, off);
            pd += __shfl_down_sync(0xffffffffu, pd, off);
        }
        if (lane == 0) {
            atomicAdd(&s_as[nbase + a], ps);
            atomicAdd(&s_ad[nbase + a], pd);
        }
    }
    __syncthreads();
    if (tid < 16) {
        int nn = node0 + tid;
        g_asv[nn] = s_as[tid];
        g_adv[nn] = s_ad[tid];
    }
}

// ---------------- GAT aggregation: softmax (no shift) + weighted sum, fused ----------------
__global__ void gat_agg_kernel(const int* __restrict__ src, const float* __restrict__ gbias) {
    __shared__ float sex[64];
    __shared__ int ssrc[64];
    int n = blockIdx.x, tid = threadIdx.x;  // 128 threads, float4 cols
    int beg = g_rowptr[n];
    int deg = g_rowptr[n + 1] - beg;
    float advn = g_adv[n];
    float exself = expf(lrelu(g_asv[n] + advn));
    const float4* h4 = (const float4*)g_h;
    float4 hs = h4[(size_t)n * 128 + tid];
    float ax = exself * hs.x, ay = exself * hs.y, az = exself * hs.z, aw = exself * hs.w;
    float dsum = exself;
    for (int base = 0; base < deg; base += 64) {
        int cnt = min(64, deg - base);
        if (tid < cnt) {
            int e = g_eidx[beg + base + tid];
            int s = src[e];
            ssrc[tid] = s;
            sex[tid] = expf(lrelu(g_asv[s] + advn));
        }
        __syncthreads();
        for (int j = 0; j < cnt; j++) {
            float exv = sex[j];
            float4 hv = h4[(size_t)ssrc[j] * 128 + tid];
            ax += exv * hv.x; ay += exv * hv.y; az += exv * hv.z; aw += exv * hv.w;
            dsum += exv;
        }
        __syncthreads();
    }
    float inv = 1.f / fmaxf(dsum, 1e-16f);
    float4 gb = ((const float4*)gbias)[tid];
    float4 o = make_float4(fmaxf(ax * inv + gb.x, 0.f), fmaxf(ay * inv + gb.y, 0.f),
                           fmaxf(az * inv + gb.z, 0.f), fmaxf(aw * inv + gb.w, 0.f));
    *(float4*)(g_gat + (size_t)n * 512 + tid * 4) = o;
}

// ---------------- edge MLP node projections: 16 nodes/block, 256 thr, 4x4 tile ----------------
__global__ void ptpb_kernel(const float* __restrict__ w1, const float* __restrict__ b1) {
    __shared__ __align__(16) float sx[16][512];
    int tid = threadIdx.x;  // 256
    int node0 = blockIdx.x * 16;
    const float4* gsrc = (const float4*)g_gat;
    for (int i = tid; i < 16 * 128; i += 256) {
        int nn = node0 + (i >> 7);
        float4 v = (nn < NN) ? gsrc[(size_t)nn * 128 + (i & 127)] : make_float4(0.f, 0.f, 0.f, 0.f);
        ((float4*)&sx[i >> 7][0])[i & 127] = v;
    }
    __syncthreads();
    int cg = tid & 63;            // 64 col groups
    int ng = tid >> 6;            // 4 node groups
    int half = cg >> 5;           // 0: top (pt), 1: bottom (pb)
    int col4 = (cg & 31) * 4;     // 0..124
    const float* wp = w1 + (half ? 512 * 128 : 0) + col4;
    int nbase = ng * 4;
    float acc[4][4];
#pragma unroll
    for (int a = 0; a < 4; a++)
#pragma unroll
        for (int b = 0; b < 4; b++) acc[a][b] = 0.f;
#pragma unroll 4
    for (int i = 0; i < 512; i++) {
        float4 wv = *(const float4*)(wp + i * 128);
        float x0 = sx[nbase + 0][i], x1 = sx[nbase + 1][i];
        float x2 = sx[nbase + 2][i], x3 = sx[nbase + 3][i];
        acc[0][0] += x0 * wv.x; acc[0][1] += x0 * wv.y; acc[0][2] += x0 * wv.z; acc[0][3] += x0 * wv.w;
        acc[1][0] += x1 * wv.x; acc[1][1] += x1 * wv.y; acc[1][2] += x1 * wv.z; acc[1][3] += x1 * wv.w;
        acc[2][0] += x2 * wv.x; acc[2][1] += x2 * wv.y; acc[2][2] += x2 * wv.z; acc[2][3] += x2 * wv.w;
        acc[3][0] += x3 * wv.x; acc[3][1] += x3 * wv.y; acc[3][2] += x3 * wv.z; acc[3][3] += x3 * wv.w;
    }
    float4 bb = half ? make_float4(0.f, 0.f, 0.f, 0.f) : *(const float4*)(b1 + col4);
    float* obase = half ? g_pb : g_pt;
#pragma unroll
    for (int a = 0; a < 4; a++) {
        int nn = node0 + nbase + a;
        if (nn < NN) {
            float4 o = make_float4(acc[a][0] + bb.x, acc[a][1] + bb.y,
                                   acc[a][2] + bb.z, acc[a][3] + bb.w);
            *(float4*)(obase + (size_t)nn * 128 + col4) = o;
        }
    }
}

__global__ void edge_out_kernel(const int* __restrict__ src, const int* __restrict__ dst,
                                const float* __restrict__ w2, const float* __restrict__ b2,
                                float* __restrict__ out) {
    int warp = (blockIdx.x * blockDim.x + threadIdx.x) >> 5;
    int lane = threadIdx.x & 31;
    if (warp >= EE) return;
    const float4* pt4 = (const float4*)(g_pt + (size_t)src[warp] * 128);
    const float4* pb4 = (const float4*)(g_pb + (size_t)dst[warp] * 128);
    const float4* w4 = (const float4*)w2;
    float4 a = pt4[lane], b = pb4[lane], w = w4[lane];
    float acc = fmaxf(a.x + b.x, 0.f) * w.x + fmaxf(a.y + b.y, 0.f) * w.y
              + fmaxf(a.z + b.z, 0.f) * w.z + fmaxf(a.w + b.w, 0.f) * w.w;
#pragma unroll
    for (int off = 16; off; off >>= 1) acc += __shfl_down_sync(0xffffffffu, acc, off);
    if (lane == 0) {
        float z = acc + b2[0];
        out[warp] = 1.f / (1.f + expf(-z));
    }
}

// ---------------- launch ----------------
extern "C" void kernel_launch(void* const* d_in, const int* in_sizes, int n_in,
                              void* d_out, int out_size) {
    int off, iE, iT;
    if (in_sizes[0] == 2 * EE) { off = 2; iE = 0; iT = 1; }
    else                       { off = 0; iE = 24; iT = 25; }
    const int* ei = (const int*)d_in[iE];
    const int* et = (const int*)d_in[iT];
    const int* src = ei;
    const int* dst = ei + EE;
    const float* basis0 = (const float*)d_in[off + 0];
    const float* comp0  = (const float*)d_in[off + 1];
    const float* root0  = (const float*)d_in[off + 2];
    const float* rbias0 = (const float*)d_in[off + 3];
    const float* basis1 = (const float*)d_in[off + 4];
    const float* comp1  = (const float*)d_in[off + 5];
    const float* root1  = (const float*)d_in[off + 6];
    const float* rbias1 = (const float*)d_in[off + 7];
    const float* basis2 = (const float*)d_in[off + 8];
    const float* comp2  = (const float*)d_in[off + 9];
    const float* root2  = (const float*)d_in[off + 10];
    const float* rbias2 = (const float*)d_in[off + 11];
    const float* basis3 = (const float*)d_in[off + 12];
    const float* comp3  = (const float*)d_in[off + 13];
    const float* root3  = (const float*)d_in[off + 14];
    const float* rbias3 = (const float*)d_in[off + 15];
    const float* gw  = (const float*)d_in[off + 16];
    const float* gas = (const float*)d_in[off + 17];
    const float* gad = (const float*)d_in[off + 18];
    const float* gb  = (const float*)d_in[off + 19];
    const float* w1  = (const float*)d_in[off + 20];
    const float* b1  = (const float*)d_in[off + 21];
    const float* w2  = (const float*)d_in[off + 22];
    const float* b2  = (const float*)d_in[off + 23];
    float* out = (float*)d_out;

    // fused precompute: relation weights + deg zeroing
    precompute_kernel<<<(PRE_TOTAL + 255) / 256, 256>>>(basis0, comp0, basis1, comp1,
                                                        basis2, comp2, basis3, comp3);
    // CSR build (by dst)
    count_kernel<<<(EE + 255) / 256, 256>>>(dst);
    scan_kernel<<<1, 1024>>>();
    scatter_kernel<<<(EE + 255) / 256, 256>>>(dst);

    // layer 0 (identity input => lookup)
    l0_agg_kernel<<<(NN * 32 + 255) / 256, 256>>>(src, et, root0, rbias0);

    // layer 1: 32 -> 64  (xA -> xB)
    dense_kernel<32, 64><<<(NN + 3) / 4, 256>>>(root1, rbias1, 0, 1);
    agg_kernel<64><<<(NN + 3) / 4, 256>>>(src, et, 1);

    // layer 2: 64 -> 64  (xB -> xA)
    dense_kernel<64, 64><<<(NN + 3) / 4, 256>>>(root2, rbias2, 1, 2);
    agg_kernel<64><<<(NN + 3) / 4, 256>>>(src, et, 0);

    // layer 3: 64 -> 32  (xA -> xB)
    dense_kernel<64, 32><<<(NN + 7) / 8, 256>>>(root3, rbias3, 0, 3);
    agg_kernel<32><<<(NN + 7) / 8, 256>>>(src, et, 1);

    // GAT (3 kernels: h + fused asv/adv, then fused softmax+agg)
    gat_h_kernel<<<(NN + 15) / 16, 512>>>(gw, gas, gad);
    gat_agg_kernel<<<NN, 128>>>(src, gb);

    // edge MLP factored through node projections
    ptpb_kernel<<<(NN + 15) / 16, 256>>>(w1, b1);
    edge_out_kernel<<<(EE * 32 + 255) / 256, 256>>>(src, dst, w2, b2, out);
}

// round 4
// speedup vs baseline: 1.2023x; 1.0277x over previous
#include <cuda_runtime.h>
#include <math.h>

#define NN 6000
#define EE 100000

// ---------------- device scratch (static, no allocation) ----------------
__device__ int g_deg[NN];          // zeroed at end of scan_kernel each launch (starts zeroed)
__device__ int g_rowptr[NN + 1];
__device__ int g_rank[EE];
__device__ int g_eidx[EE];

__device__ __align__(16) float g_W0[2 * NN * 32];
__device__ __align__(16) float g_Wl1[2 * 32 * 64];
__device__ __align__(16) float g_Wl2[2 * 64 * 64];
__device__ __align__(16) float g_Wl3[2 * 64 * 32];
__device__ __align__(16) float g_hrA[2 * NN * 64];   // layers 1 (64-wide) and 3 (32-wide)
__device__ __align__(16) float g_hrB[2 * NN * 64];   // layer 2 (64-wide)
__device__ __align__(16) float g_rootout[NN * 64];   // layers 1,2
__device__ __align__(16) float g_rootout3[NN * 32];  // layer 3 (separate: width change would alias)
__device__ __align__(16) float g_xB[NN * 32];        // RGCN output (input to GAT)

__device__ __align__(16) float g_h[NN * 512];        // GAT hidden
__device__ float g_asv[NN], g_adv[NN];
__device__ __align__(16) float g_pt[NN * 128];       // gat_out @ w1[0:512] (+ b1)
__device__ __align__(16) float g_pb[NN * 128];       // gat_out @ w1[512:1024]

__device__ __forceinline__ float lrelu(float v) { return v > 0.f ? v : 0.2f * v; }

// ---------------- kernel 1: relation-weight precompute + degree count (fused) ----------------
#define W0_CNT (2 * NN * 32)
#define WL1_CNT (2 * 32 * 64)
#define WL2_CNT (2 * 64 * 64)
#define WL3_CNT (2 * 64 * 32)
#define PRE_CNT (W0_CNT + WL1_CNT + WL2_CNT + WL3_CNT)
#define PRE_BLOCKS (PRE_CNT / 256)              // 400384/256 = 1564 exactly
#define CNT_BLOCKS ((EE + 255) / 256)

__global__ void pre_count_kernel(const float* __restrict__ basis0, const float* __restrict__ comp0,
                                 const float* __restrict__ basis1, const float* __restrict__ comp1,
                                 const float* __restrict__ basis2, const float* __restrict__ comp2,
                                 const float* __restrict__ basis3, const float* __restrict__ comp3,
                                 const int* __restrict__ dst) {
    int bid = blockIdx.x;
    if (bid >= PRE_BLOCKS) {
        int e = (bid - PRE_BLOCKS) * 256 + threadIdx.x;
        if (e < EE) g_rank[e] = atomicAdd(&g_deg[dst[e]], 1);
        return;
    }
    int idx = bid * 256 + threadIdx.x;
    if (idx < W0_CNT) {
        int per = NN * 32;
        int r = idx / per, rem = idx - r * per;
        float v = 0.f;
#pragma unroll
        for (int b = 0; b < 4; b++) v += comp0[r * 4 + b] * basis0[b * per + rem];
        g_W0[idx] = v;
        return;
    }
    idx -= W0_CNT;
    if (idx < WL1_CNT) {
        int per = 32 * 64;
        int r = idx / per, rem = idx - r * per;
        float v = 0.f;
#pragma unroll
        for (int b = 0; b < 4; b++) v += comp1[r * 4 + b] * basis1[b * per + rem];
        g_Wl1[idx] = v;
        return;
    }
    idx -= WL1_CNT;
    if (idx < WL2_CNT) {
        int per = 64 * 64;
        int r = idx / per, rem = idx - r * per;
        float v = 0.f;
#pragma unroll
        for (int b = 0; b < 4; b++) v += comp2[r * 4 + b] * basis2[b * per + rem];
        g_Wl2[idx] = v;
        return;
    }
    idx -= WL2_CNT;
    {
        int per = 64 * 32;
        int r = idx / per, rem = idx - r * per;
        float v = 0.f;
#pragma unroll
        for (int b = 0; b < 4; b++) v += comp3[r * 4 + b] * basis3[b * per + rem];
        g_Wl3[idx] = v;
    }
}

// ---------------- kernel 2: single-pass scan (also re-zeroes deg for next launch) ----------------
__global__ void scan_kernel() {
    __shared__ int swsum[32];
    int tid = threadIdx.x, lane = tid & 31, wid = tid >> 5;
    int base = tid * 6;
    int v[6];
    int s = 0;
#pragma unroll
    for (int j = 0; j < 6; j++) {
        int i = base + j;
        v[j] = (i < NN) ? g_deg[i] : 0;
        s += v[j];
    }
    int x = s;
#pragma unroll
    for (int off = 1; off < 32; off <<= 1) {
        int t = __shfl_up_sync(0xffffffffu, x, off);
        if (lane >= off) x += t;
    }
    if (lane == 31) swsum[wid] = x;
    __syncthreads();
    if (wid == 0) {
        int y = swsum[lane];
#pragma unroll
        for (int off = 1; off < 32; off <<= 1) {
            int t = __shfl_up_sync(0xffffffffu, y, off);
            if (lane >= off) y += t;
        }
        swsum[lane] = y;
    }
    __syncthreads();
    int run = x - s + (wid ? swsum[wid - 1] : 0);
#pragma unroll
    for (int j = 0; j < 6; j++) {
        int i = base + j;
        run += v[j];
        if (i < NN) g_rowptr[i + 1] = run;
    }
    if (tid == 0) g_rowptr[0] = 0;
#pragma unroll
    for (int j = 0; j < 6; j++) {
        int i = base + j;
        if (i < NN) g_deg[i] = 0;   // restore invariant for next launch
    }
}

// ---------------- kernel 3: atomic-free scatter ----------------
__global__ void scatter_kernel(const int* __restrict__ dst) {
    int e = blockIdx.x * blockDim.x + threadIdx.x;
    if (e < EE) g_eidx[g_rowptr[dst[e]] + g_rank[e]] = e;
}

// ---------------- kernel 4: layer-0 agg (identity input) + dense1 fused ----------------
__global__ void l0d1_kernel(const int* __restrict__ src, const int* __restrict__ et,
                            const float* __restrict__ root0, const float* __restrict__ rbias0,
                            const float* __restrict__ root1, const float* __restrict__ rbias1) {
    __shared__ float sx[8][32];
    int tid = threadIdx.x, w = tid >> 5, lane = tid & 31;
    int node = blockIdx.x * 8 + w;
    {
        int beg = g_rowptr[node], end = g_rowptr[node + 1];
        float a0 = 0.f, a1 = 0.f, c0 = 0.f, c1 = 0.f;
        for (int k = beg; k < end; k++) {
            int e = g_eidx[k];
            int s = src[e];
            int t = et[e];
            float v = g_W0[t * (NN * 32) + s * 32 + lane];
            if (t == 0) { a0 += v; c0 += 1.f; } else { a1 += v; c1 += 1.f; }
        }
        float out = root0[node * 32 + lane] + rbias0[lane]
                  + a0 / fmaxf(c0, 1.f) + a1 / fmaxf(c1, 1.f);
        sx[w][lane] = tanhf(out);
    }
    __syncthreads();
    // dense1: 32 -> 64, three matrices; 8*64=512 outputs, 2 per thread
#pragma unroll
    for (int t = tid; t < 512; t += 256) {
        int ln = t >> 6, o = t & 63;
        int nn = blockIdx.x * 8 + ln;
        float a0 = 0.f, a1 = 0.f, ar = 0.f;
#pragma unroll 8
        for (int i = 0; i < 32; i++) {
            float xv = sx[ln][i];
            a0 += xv * g_Wl1[i * 64 + o];
            a1 += xv * g_Wl1[32 * 64 + i * 64 + o];
            ar += xv * root1[i * 64 + o];
        }
        g_hrA[nn * 64 + o] = a0;
        g_hrA[NN * 64 + nn * 64 + o] = a1;
        g_rootout[nn * 64 + o] = ar + rbias1[o];
    }
}

// ---------------- kernel 5: agg1 (reads hrA) + dense2 (writes hrB) fused ----------------
__global__ void a1d2_kernel(const int* __restrict__ src, const int* __restrict__ et,
                            const float* __restrict__ root2, const float* __restrict__ rbias2) {
    __shared__ float sx[4][64];
    int tid = threadIdx.x;
    int ln = tid >> 6, o = tid & 63;
    int node = blockIdx.x * 4 + ln;
    {
        int beg = g_rowptr[node], end = g_rowptr[node + 1];
        float a0 = 0.f, a1 = 0.f, c0 = 0.f, c1 = 0.f;
        for (int k = beg; k < end; k++) {
            int e = g_eidx[k];
            int s = src[e];
            int t = et[e];
            float v = g_hrA[t * (NN * 64) + s * 64 + o];
            if (t == 0) { a0 += v; c0 += 1.f; } else { a1 += v; c1 += 1.f; }
        }
        float out = g_rootout[node * 64 + o] + a0 / fmaxf(c0, 1.f) + a1 / fmaxf(c1, 1.f);
        sx[ln][o] = tanhf(out);
    }
    __syncthreads();
    // dense2: 64 -> 64
    float a0 = 0.f, a1 = 0.f, ar = 0.f;
#pragma unroll 8
    for (int i = 0; i < 64; i++) {
        float xv = sx[ln][i];
        a0 += xv * g_Wl2[i * 64 + o];
        a1 += xv * g_Wl2[64 * 64 + i * 64 + o];
        ar += xv * root2[i * 64 + o];
    }
    g_hrB[node * 64 + o] = a0;
    g_hrB[NN * 64 + node * 64 + o] = a1;
    g_rootout[node * 64 + o] = ar + rbias2[o];
}

// ---------------- kernel 6: agg2 (reads hrB) + dense3 (writes hrA 32-wide) fused ----------------
__global__ void a2d3_kernel(const int* __restrict__ src, const int* __restrict__ et,
                            const float* __restrict__ root3, const float* __restrict__ rbias3) {
    __shared__ float sx[4][64];
    int tid = threadIdx.x;
    int ln = tid >> 6, o = tid & 63;
    int node = blockIdx.x * 4 + ln;
    {
        int beg = g_rowptr[node], end = g_rowptr[node + 1];
        float a0 = 0.f, a1 = 0.f, c0 = 0.f, c1 = 0.f;
        for (int k = beg; k < end; k++) {
            int e = g_eidx[k];
            int s = src[e];
            int t = et[e];
            float v = g_hrB[t * (NN * 64) + s * 64 + o];
            if (t == 0) { a0 += v; c0 += 1.f; } else { a1 += v; c1 += 1.f; }
        }
        float out = g_rootout[node * 64 + o] + a0 / fmaxf(c0, 1.f) + a1 / fmaxf(c1, 1.f);
        sx[ln][o] = tanhf(out);
    }
    __syncthreads();
    // dense3: 64 -> 32 (threads 0..127)
    if (tid < 128) {
        int ln3 = tid >> 5, o3 = tid & 31;
        int nn = blockIdx.x * 4 + ln3;
        float a0 = 0.f, a1 = 0.f, ar = 0.f;
#pragma unroll 8
        for (int i = 0; i < 64; i++) {
            float xv = sx[ln3][i];
            a0 += xv * g_Wl3[i * 32 + o3];
            a1 += xv * g_Wl3[64 * 32 + i * 32 + o3];
            ar += xv * root3[i * 32 + o3];
        }
        g_hrA[nn * 32 + o3] = a0;
        g_hrA[NN * 32 + nn * 32 + o3] = a1;
        g_rootout3[nn * 32 + o3] = ar + rbias3[o3];
    }
}

// ---------------- kernel 7: agg3 -> g_xB ----------------
__global__ void agg3_kernel(const int* __restrict__ src, const int* __restrict__ et) {
    int tid = threadIdx.x;
    int ln = tid >> 5, o = tid & 31;
    int node = blockIdx.x * 8 + ln;
    int beg = g_rowptr[node], end = g_rowptr[node + 1];
    float a0 = 0.f, a1 = 0.f, c0 = 0.f, c1 = 0.f;
    for (int k = beg; k < end; k++) {
        int e = g_eidx[k];
        int s = src[e];
        int t = et[e];
        float v = g_hrA[t * (NN * 32) + s * 32 + o];
        if (t == 0) { a0 += v; c0 += 1.f; } else { a1 += v; c1 += 1.f; }
    }
    float out = g_rootout3[node * 32 + o] + a0 / fmaxf(c0, 1.f) + a1 / fmaxf(c1, 1.f);
    g_xB[node * 32 + o] = tanhf(out);
}

// ---------------- kernel 8: GAT h = x @ gat_w + fused asv/adv ----------------
__global__ void gat_h_kernel(const float* __restrict__ gw,
                             const float* __restrict__ as, const float* __restrict__ ad) {
    __shared__ __align__(16) float sx[16][32];
    __shared__ float s_as[16], s_ad[16];
    int tid = threadIdx.x;  // 512
    int node0 = blockIdx.x * 16;
    for (int i = tid; i < 16 * 32; i += 512) {
        int nn = node0 + (i >> 5);
        sx[i >> 5][i & 31] = (nn < NN) ? g_xB[nn * 32 + (i & 31)] : 0.f;
    }
    if (tid < 16) { s_as[tid] = 0.f; s_ad[tid] = 0.f; }
    __syncthreads();
    int cg = tid & 127;
    int ng = tid >> 7;
    int col4 = cg * 4;
    int nbase = ng * 4;
    float acc[4][4];
#pragma unroll
    for (int a = 0; a < 4; a++)
#pragma unroll
        for (int b = 0; b < 4; b++) acc[a][b] = 0.f;
#pragma unroll 8
    for (int i = 0; i < 32; i++) {
        float4 wv = *(const float4*)(gw + i * 512 + col4);
        float x0 = sx[nbase + 0][i], x1 = sx[nbase + 1][i];
        float x2 = sx[nbase + 2][i], x3 = sx[nbase + 3][i];
        acc[0][0] += x0 * wv.x; acc[0][1] += x0 * wv.y; acc[0][2] += x0 * wv.z; acc[0][3] += x0 * wv.w;
        acc[1][0] += x1 * wv.x; acc[1][1] += x1 * wv.y; acc[1][2] += x1 * wv.z; acc[1][3] += x1 * wv.w;
        acc[2][0] += x2 * wv.x; acc[2][1] += x2 * wv.y; acc[2][2] += x2 * wv.z; acc[2][3] += x2 * wv.w;
        acc[3][0] += x3 * wv.x; acc[3][1] += x3 * wv.y; acc[3][2] += x3 * wv.z; acc[3][3] += x3 * wv.w;
    }
#pragma unroll
    for (int a = 0; a < 4; a++) {
        int nn = node0 + nbase + a;
        float4 o = make_float4(acc[a][0], acc[a][1], acc[a][2], acc[a][3]);
        *(float4*)(g_h + (size_t)nn * 512 + col4) = o;
    }
    float4 av = *(const float4*)(as + col4);
    float4 dv = *(const float4*)(ad + col4);
    int lane = tid & 31;
#pragma unroll
    for (int a = 0; a < 4; a++) {
        float ps = acc[a][0] * av.x + acc[a][1] * av.y + acc[a][2] * av.z + acc[a][3] * av.w;
        float pd = acc[a][0] * dv.x + acc[a][1] * dv.y + acc[a][2] * dv.z + acc[a][3] * dv.w;
#pragma unroll
        for (int off = 16; off; off >>= 1) {
            ps += __shfl_down_sync(0xffffffffu, ps, off);
            pd += __shfl_down_sync(0xffffffffu, pd, off);
        }
        if (lane == 0) {
            atomicAdd(&s_as[nbase + a], ps);
            atomicAdd(&s_ad[nbase + a], pd);
        }
    }
    __syncthreads();
    if (tid < 16) {
        int nn = node0 + tid;
        g_asv[nn] = s_as[tid];
        g_adv[nn] = s_ad[tid];
    }
}

// ---------------- kernel 9: GAT softmax-agg + edge-MLP node projection, fused ----------------
// 16 nodes/block, 256 threads = 2 groups of 128 (4 warps each, named barriers 1/2).
// Aggregation results land directly in the smem tile the GEMM phase consumes.
__global__ void gatagg_ptpb_kernel(const int* __restrict__ src, const float* __restrict__ gbias,
                                   const float* __restrict__ w1, const float* __restrict__ b1) {
    __shared__ __align__(16) float sx[16][512];
    __shared__ float sex[2][64];
    __shared__ int ssrc[2][64];
    int tid = threadIdx.x;
    int node0 = blockIdx.x * 16;
    int g = tid >> 7;          // group 0/1
    int gtid = tid & 127;
    const float4* h4 = (const float4*)g_h;
    float4 gb4 = ((const float4*)gbias)[gtid];
    for (int k = 0; k < 8; k++) {
        int n = node0 + g * 8 + k;
        int beg = g_rowptr[n], deg = g_rowptr[n + 1] - beg;
        float advn = g_adv[n];
        float exself = expf(lrelu(g_asv[n] + advn));
        float4 hs = h4[(size_t)n * 128 + gtid];
        float ax = exself * hs.x, ay = exself * hs.y, az = exself * hs.z, aw = exself * hs.w;
        float dsum = exself;
        for (int base = 0; base < deg; base += 64) {
            int cnt = min(64, deg - base);
            if (gtid < cnt) {
                int e = g_eidx[beg + base + gtid];
                int s = src[e];
                ssrc[g][gtid] = s;
                sex[g][gtid] = expf(lrelu(g_asv[s] + advn));
            }
            asm volatile("bar.sync %0, %1;" :: "r"(g + 1), "r"(128) : "memory");
            for (int j = 0; j < cnt; j++) {
                float exv = sex[g][j];
                float4 hv = h4[(size_t)ssrc[g][j] * 128 + gtid];
                ax += exv * hv.x; ay += exv * hv.y; az += exv * hv.z; aw += exv * hv.w;
                dsum += exv;
            }
            asm volatile("bar.sync %0, %1;" :: "r"(g + 1), "r"(128) : "memory");
        }
        float inv = 1.f / fmaxf(dsum, 1e-16f);
        float4 o = make_float4(fmaxf(ax * inv + gb4.x, 0.f), fmaxf(ay * inv + gb4.y, 0.f),
                               fmaxf(az * inv + gb4.z, 0.f), fmaxf(aw * inv + gb4.w, 0.f));
        ((float4*)sx[g * 8 + k])[gtid] = o;
    }
    __syncthreads();
    // GEMM phase: 1024 -> 256 projection split as two 512-col halves
    int cg = tid & 63;
    int ng = tid >> 6;
    int half = cg >> 5;
    int col4 = (cg & 31) * 4;
    const float* wp = w1 + (half ? 512 * 128 : 0) + col4;
    int nbase = ng * 4;
    float acc[4][4];
#pragma unroll
    for (int a = 0; a < 4; a++)
#pragma unroll
        for (int b = 0; b < 4; b++) acc[a][b] = 0.f;
#pragma unroll 4
    for (int i = 0; i < 512; i++) {
        float4 wv = *(const float4*)(wp + i * 128);
        float x0 = sx[nbase + 0][i], x1 = sx[nbase + 1][i];
        float x2 = sx[nbase + 2][i], x3 = sx[nbase + 3][i];
        acc[0][0] += x0 * wv.x; acc[0][1] += x0 * wv.y; acc[0][2] += x0 * wv.z; acc[0][3] += x0 * wv.w;
        acc[1][0] += x1 * wv.x; acc[1][1] += x1 * wv.y; acc[1][2] += x1 * wv.z; acc[1][3] += x1 * wv.w;
        acc[2][0] += x2 * wv.x; acc[2][1] += x2 * wv.y; acc[2][2] += x2 * wv.z; acc[2][3] += x2 * wv.w;
        acc[3][0] += x3 * wv.x; acc[3][1] += x3 * wv.y; acc[3][2] += x3 * wv.z; acc[3][3] += x3 * wv.w;
    }
    float4 bb = half ? make_float4(0.f, 0.f, 0.f, 0.f) : *(const float4*)(b1 + col4);
    float* obase = half ? g_pb : g_pt;
#pragma unroll
    for (int a = 0; a < 4; a++) {
        int nn = node0 + nbase + a;
        float4 o = make_float4(acc[a][0] + bb.x, acc[a][1] + bb.y,
                               acc[a][2] + bb.z, acc[a][3] + bb.w);
        *(float4*)(obase + (size_t)nn * 128 + col4) = o;
    }
}

// ---------------- kernel 10: per-edge output ----------------
__global__ void edge_out_kernel(const int* __restrict__ src, const int* __restrict__ dst,
                                const float* __restrict__ w2, const float* __restrict__ b2,
                                float* __restrict__ out) {
    int warp = (blockIdx.x * blockDim.x + threadIdx.x) >> 5;
    int lane = threadIdx.x & 31;
    if (warp >= EE) return;
    const float4* pt4 = (const float4*)(g_pt + (size_t)src[warp] * 128);
    const float4* pb4 = (const float4*)(g_pb + (size_t)dst[warp] * 128);
    const float4* w4 = (const float4*)w2;
    float4 a = pt4[lane], b = pb4[lane], w = w4[lane];
    float acc = fmaxf(a.x + b.x, 0.f) * w.x + fmaxf(a.y + b.y, 0.f) * w.y
              + fmaxf(a.z + b.z, 0.f) * w.z + fmaxf(a.w + b.w, 0.f) * w.w;
#pragma unroll
    for (int off = 16; off; off >>= 1) acc += __shfl_down_sync(0xffffffffu, acc, off);
    if (lane == 0) {
        float z = acc + b2[0];
        out[warp] = 1.f / (1.f + expf(-z));
    }
}

// ---------------- launch ----------------
extern "C" void kernel_launch(void* const* d_in, const int* in_sizes, int n_in,
                              void* d_out, int out_size) {
    int off, iE, iT;
    if (in_sizes[0] == 2 * EE) { off = 2; iE = 0; iT = 1; }
    else                       { off = 0; iE = 24; iT = 25; }
    const int* ei = (const int*)d_in[iE];
    const int* et = (const int*)d_in[iT];
    const int* src = ei;
    const int* dst = ei + EE;
    const float* basis0 = (const float*)d_in[off + 0];
    const float* comp0  = (const float*)d_in[off + 1];
    const float* root0  = (const float*)d_in[off + 2];
    const float* rbias0 = (const float*)d_in[off + 3];
    const float* basis1 = (const float*)d_in[off + 4];
    const float* comp1  = (const float*)d_in[off + 5];
    const float* root1  = (const float*)d_in[off + 6];
    const float* rbias1 = (const float*)d_in[off + 7];
    const float* basis2 = (const float*)d_in[off + 8];
    const float* comp2  = (const float*)d_in[off + 9];
    const float* root2  = (const float*)d_in[off + 10];
    const float* rbias2 = (const float*)d_in[off + 11];
    const float* basis3 = (const float*)d_in[off + 12];
    const float* comp3  = (const float*)d_in[off + 13];
    const float* root3  = (const float*)d_in[off + 14];
    const float* rbias3 = (const float*)d_in[off + 15];
    const float* gw  = (const float*)d_in[off + 16];
    const float* gas = (const float*)d_in[off + 17];
    const float* gad = (const float*)d_in[off + 18];
    const float* gb  = (const float*)d_in[off + 19];
    const float* w1  = (const float*)d_in[off + 20];
    const float* b1  = (const float*)d_in[off + 21];
    const float* w2  = (const float*)d_in[off + 22];
    const float* b2  = (const float*)d_in[off + 23];
    float* out = (float*)d_out;

    // 1: relation weights + degree count (deg==0 invariant from previous scan / initial state)
    pre_count_kernel<<<PRE_BLOCKS + CNT_BLOCKS, 256>>>(basis0, comp0, basis1, comp1,
                                                       basis2, comp2, basis3, comp3, dst);
    // 2: rowptr scan (re-zeroes deg)
    scan_kernel<<<1, 1024>>>();
    // 3: atomic-free scatter
    scatter_kernel<<<CNT_BLOCKS, 256>>>(dst);

    // 4-7: RGCN chain with dense fused into preceding agg
    l0d1_kernel<<<NN / 8, 256>>>(src, et, root0, rbias0, root1, rbias1);
    a1d2_kernel<<<NN / 4, 256>>>(src, et, root2, rbias2);
    a2d3_kernel<<<NN / 4, 256>>>(src, et, root3, rbias3);
    agg3_kernel<<<NN / 8, 256>>>(src, et);

    // 8: GAT hidden + attention logits
    gat_h_kernel<<<NN / 16, 512>>>(gw, gas, gad);
    // 9: GAT softmax-aggregate + w1 projection (fused, no g_gat round trip)
    gatagg_ptpb_kernel<<<NN / 16, 256>>>(src, gb, w1, b1);
    // 10: per-edge output
    edge_out_kernel<<<(EE * 32 + 255) / 256, 256>>>(src, dst, w2, b2, out);
}

// round 5
// speedup vs baseline: 1.2520x; 1.0413x over previous
#include <cuda_runtime.h>
#include <math.h>

#define NN 6000
#define EE 100000

// ---------------- device scratch (static, no allocation) ----------------
__device__ int g_deg[NN];          // zeroed at end of scan_kernel each launch (starts zeroed)
__device__ int g_rowptr[NN + 1];
__device__ int g_rank[EE];
__device__ int g_es[EE];           // packed per CSR slot: e | (src<<17) | (type<<30)

__device__ __align__(16) float g_W0[2 * NN * 32];
__device__ __align__(16) float g_Wl1[2 * 32 * 64];
__device__ __align__(16) float g_Wl2[2 * 64 * 64];
__device__ __align__(16) float g_Wl3[2 * 64 * 32];
__device__ __align__(16) float g_hrA[2 * NN * 64];   // layers 1 (64-wide) and 3 (32-wide)
__device__ __align__(16) float g_hrB[2 * NN * 64];   // layer 2 (64-wide)
__device__ __align__(16) float g_rootout[NN * 64];   // layers 1,2
__device__ __align__(16) float g_rootout3[NN * 32];  // layer 3
__device__ __align__(16) float g_h[NN * 512];        // GAT hidden
__device__ float g_asv[NN], g_adv[NN];
__device__ __align__(16) float g_pt[NN * 128];       // gat_out @ w1[0:512] (+ b1)
__device__ __align__(16) float g_pb[NN * 128];       // gat_out @ w1[512:1024]

__device__ __forceinline__ float lrelu(float v) { return v > 0.f ? v : 0.2f * v; }

// ---------------- kernel 1: relation-weight precompute + degree count (fused) ----------------
#define W0_CNT (2 * NN * 32)
#define WL1_CNT (2 * 32 * 64)
#define WL2_CNT (2 * 64 * 64)
#define WL3_CNT (2 * 64 * 32)
#define PRE_CNT (W0_CNT + WL1_CNT + WL2_CNT + WL3_CNT)
#define PRE_BLOCKS (PRE_CNT / 256)
#define CNT_BLOCKS ((EE + 255) / 256)

__global__ void pre_count_kernel(const float* __restrict__ basis0, const float* __restrict__ comp0,
                                 const float* __restrict__ basis1, const float* __restrict__ comp1,
                                 const float* __restrict__ basis2, const float* __restrict__ comp2,
                                 const float* __restrict__ basis3, const float* __restrict__ comp3,
                                 const int* __restrict__ dst) {
    int bid = blockIdx.x;
    if (bid >= PRE_BLOCKS) {
        int e = (bid - PRE_BLOCKS) * 256 + threadIdx.x;
        if (e < EE) g_rank[e] = atomicAdd(&g_deg[dst[e]], 1);
        return;
    }
    int idx = bid * 256 + threadIdx.x;
    if (idx < W0_CNT) {
        int per = NN * 32;
        int r = idx / per, rem = idx - r * per;
        float v = 0.f;
#pragma unroll
        for (int b = 0; b < 4; b++) v += comp0[r * 4 + b] * basis0[b * per + rem];
        g_W0[idx] = v;
        return;
    }
    idx -= W0_CNT;
    if (idx < WL1_CNT) {
        int per = 32 * 64;
        int r = idx / per, rem = idx - r * per;
        float v = 0.f;
#pragma unroll
        for (int b = 0; b < 4; b++) v += comp1[r * 4 + b] * basis1[b * per + rem];
        g_Wl1[idx] = v;
        return;
    }
    idx -= WL1_CNT;
    if (idx < WL2_CNT) {
        int per = 64 * 64;
        int r = idx / per, rem = idx - r * per;
        float v = 0.f;
#pragma unroll
        for (int b = 0; b < 4; b++) v += comp2[r * 4 + b] * basis2[b * per + rem];
        g_Wl2[idx] = v;
        return;
    }
    idx -= WL2_CNT;
    {
        int per = 64 * 32;
        int r = idx / per, rem = idx - r * per;
        float v = 0.f;
#pragma unroll
        for (int b = 0; b < 4; b++) v += comp3[r * 4 + b] * basis3[b * per + rem];
        g_Wl3[idx] = v;
    }
}

// ---------------- kernel 2: single-pass scan (also re-zeroes deg) ----------------
__global__ void scan_kernel() {
    __shared__ int swsum[32];
    int tid = threadIdx.x, lane = tid & 31, wid = tid >> 5;
    int base = tid * 6;
    int v[6];
    int s = 0;
#pragma unroll
    for (int j = 0; j < 6; j++) {
        int i = base + j;
        v[j] = (i < NN) ? g_deg[i] : 0;
        s += v[j];
    }
    int x = s;
#pragma unroll
    for (int off = 1; off < 32; off <<= 1) {
        int t = __shfl_up_sync(0xffffffffu, x, off);
        if (lane >= off) x += t;
    }
    if (lane == 31) swsum[wid] = x;
    __syncthreads();
    if (wid == 0) {
        int y = swsum[lane];
#pragma unroll
        for (int off = 1; off < 32; off <<= 1) {
            int t = __shfl_up_sync(0xffffffffu, y, off);
            if (lane >= off) y += t;
        }
        swsum[lane] = y;
    }
    __syncthreads();
    int run = x - s + (wid ? swsum[wid - 1] : 0);
#pragma unroll
    for (int j = 0; j < 6; j++) {
        int i = base + j;
        run += v[j];
        if (i < NN) g_rowptr[i + 1] = run;
    }
    if (tid == 0) g_rowptr[0] = 0;
#pragma unroll
    for (int j = 0; j < 6; j++) {
        int i = base + j;
        if (i < NN) g_deg[i] = 0;
    }
}

// ---------------- kernel 3: atomic-free scatter, packed slot ----------------
__global__ void scatter_kernel(const int* __restrict__ src, const int* __restrict__ dst,
                               const int* __restrict__ et) {
    int e = blockIdx.x * blockDim.x + threadIdx.x;
    if (e < EE) {
        int p = g_rowptr[dst[e]] + g_rank[e];
        g_es[p] = e | (src[e] << 17) | (et[e] << 30);
    }
}

#define ES_S(v) (((v) >> 17) & 0x1FFF)
#define ES_T(v) (((v) >> 30) & 1)
#define ES_E(v) ((v) & 0x1FFFF)

// ---------------- kernel 4: layer-0 agg (identity input) + dense1 fused ----------------
__global__ void l0d1_kernel(const float* __restrict__ root0, const float* __restrict__ rbias0,
                            const float* __restrict__ root1, const float* __restrict__ rbias1) {
    __shared__ float sx[8][32];
    int tid = threadIdx.x, w = tid >> 5, lane = tid & 31;
    int node = blockIdx.x * 8 + w;
    {
        int beg = g_rowptr[node], end = g_rowptr[node + 1];
        float a0 = 0.f, a1 = 0.f, c0 = 0.f, c1 = 0.f;
        int k = beg;
        for (; k + 4 <= end; k += 4) {
            int v0 = g_es[k], v1 = g_es[k + 1], v2 = g_es[k + 2], v3 = g_es[k + 3];
            float f0 = g_W0[ES_T(v0) * (NN * 32) + ES_S(v0) * 32 + lane];
            float f1 = g_W0[ES_T(v1) * (NN * 32) + ES_S(v1) * 32 + lane];
            float f2 = g_W0[ES_T(v2) * (NN * 32) + ES_S(v2) * 32 + lane];
            float f3 = g_W0[ES_T(v3) * (NN * 32) + ES_S(v3) * 32 + lane];
            if (ES_T(v0)) { a1 += f0; c1 += 1.f; } else { a0 += f0; c0 += 1.f; }
            if (ES_T(v1)) { a1 += f1; c1 += 1.f; } else { a0 += f1; c0 += 1.f; }
            if (ES_T(v2)) { a1 += f2; c1 += 1.f; } else { a0 += f2; c0 += 1.f; }
            if (ES_T(v3)) { a1 += f3; c1 += 1.f; } else { a0 += f3; c0 += 1.f; }
        }
        for (; k < end; k++) {
            int v = g_es[k];
            float f = g_W0[ES_T(v) * (NN * 32) + ES_S(v) * 32 + lane];
            if (ES_T(v)) { a1 += f; c1 += 1.f; } else { a0 += f; c0 += 1.f; }
        }
        float out = root0[node * 32 + lane] + rbias0[lane]
                  + a0 / fmaxf(c0, 1.f) + a1 / fmaxf(c1, 1.f);
        sx[w][lane] = tanhf(out);
    }
    __syncthreads();
#pragma unroll
    for (int t = tid; t < 512; t += 256) {
        int ln = t >> 6, o = t & 63;
        int nn = blockIdx.x * 8 + ln;
        float a0 = 0.f, a1 = 0.f, ar = 0.f;
#pragma unroll 8
        for (int i = 0; i < 32; i++) {
            float xv = sx[ln][i];
            a0 += xv * g_Wl1[i * 64 + o];
            a1 += xv * g_Wl1[32 * 64 + i * 64 + o];
            ar += xv * root1[i * 64 + o];
        }
        g_hrA[nn * 64 + o] = a0;
        g_hrA[NN * 64 + nn * 64 + o] = a1;
        g_rootout[nn * 64 + o] = ar + rbias1[o];
    }
}

// ---------------- kernel 5: agg1 + dense2 fused ----------------
__global__ void a1d2_kernel(const float* __restrict__ root2, const float* __restrict__ rbias2) {
    __shared__ float sx[4][64];
    int tid = threadIdx.x;
    int ln = tid >> 6, o = tid & 63;
    int node = blockIdx.x * 4 + ln;
    {
        int beg = g_rowptr[node], end = g_rowptr[node + 1];
        float a0 = 0.f, a1 = 0.f, c0 = 0.f, c1 = 0.f;
        int k = beg;
        for (; k + 4 <= end; k += 4) {
            int v0 = g_es[k], v1 = g_es[k + 1], v2 = g_es[k + 2], v3 = g_es[k + 3];
            float f0 = g_hrA[ES_T(v0) * (NN * 64) + ES_S(v0) * 64 + o];
            float f1 = g_hrA[ES_T(v1) * (NN * 64) + ES_S(v1) * 64 + o];
            float f2 = g_hrA[ES_T(v2) * (NN * 64) + ES_S(v2) * 64 + o];
            float f3 = g_hrA[ES_T(v3) * (NN * 64) + ES_S(v3) * 64 + o];
            if (ES_T(v0)) { a1 += f0; c1 += 1.f; } else { a0 += f0; c0 += 1.f; }
            if (ES_T(v1)) { a1 += f1; c1 += 1.f; } else { a0 += f1; c0 += 1.f; }
            if (ES_T(v2)) { a1 += f2; c1 += 1.f; } else { a0 += f2; c0 += 1.f; }
            if (ES_T(v3)) { a1 += f3; c1 += 1.f; } else { a0 += f3; c0 += 1.f; }
        }
        for (; k < end; k++) {
            int v = g_es[k];
            float f = g_hrA[ES_T(v) * (NN * 64) + ES_S(v) * 64 + o];
            if (ES_T(v)) { a1 += f; c1 += 1.f; } else { a0 += f; c0 += 1.f; }
        }
        float out = g_rootout[node * 64 + o] + a0 / fmaxf(c0, 1.f) + a1 / fmaxf(c1, 1.f);
        sx[ln][o] = tanhf(out);
    }
    __syncthreads();
    float a0 = 0.f, a1 = 0.f, ar = 0.f;
#pragma unroll 8
    for (int i = 0; i < 64; i++) {
        float xv = sx[ln][i];
        a0 += xv * g_Wl2[i * 64 + o];
        a1 += xv * g_Wl2[64 * 64 + i * 64 + o];
        ar += xv * root2[i * 64 + o];
    }
    g_hrB[node * 64 + o] = a0;
    g_hrB[NN * 64 + node * 64 + o] = a1;
    g_rootout[node * 64 + o] = ar + rbias2[o];
}

// ---------------- kernel 6: agg2 + dense3 fused ----------------
__global__ void a2d3_kernel(const float* __restrict__ root3, const float* __restrict__ rbias3) {
    __shared__ float sx[4][64];
    int tid = threadIdx.x;
    int ln = tid >> 6, o = tid & 63;
    int node = blockIdx.x * 4 + ln;
    {
        int beg = g_rowptr[node], end = g_rowptr[node + 1];
        float a0 = 0.f, a1 = 0.f, c0 = 0.f, c1 = 0.f;
        int k = beg;
        for (; k + 4 <= end; k += 4) {
            int v0 = g_es[k], v1 = g_es[k + 1], v2 = g_es[k + 2], v3 = g_es[k + 3];
            float f0 = g_hrB[ES_T(v0) * (NN * 64) + ES_S(v0) * 64 + o];
            float f1 = g_hrB[ES_T(v1) * (NN * 64) + ES_S(v1) * 64 + o];
            float f2 = g_hrB[ES_T(v2) * (NN * 64) + ES_S(v2) * 64 + o];
            float f3 = g_hrB[ES_T(v3) * (NN * 64) + ES_S(v3) * 64 + o];
            if (ES_T(v0)) { a1 += f0; c1 += 1.f; } else { a0 += f0; c0 += 1.f; }
            if (ES_T(v1)) { a1 += f1; c1 += 1.f; } else { a0 += f1; c0 += 1.f; }
            if (ES_T(v2)) { a1 += f2; c1 += 1.f; } else { a0 += f2; c0 += 1.f; }
            if (ES_T(v3)) { a1 += f3; c1 += 1.f; } else { a0 += f3; c0 += 1.f; }
        }
        for (; k < end; k++) {
            int v = g_es[k];
            float f = g_hrB[ES_T(v) * (NN * 64) + ES_S(v) * 64 + o];
            if (ES_T(v)) { a1 += f; c1 += 1.f; } else { a0 += f; c0 += 1.f; }
        }
        float out = g_rootout[node * 64 + o] + a0 / fmaxf(c0, 1.f) + a1 / fmaxf(c1, 1.f);
        sx[ln][o] = tanhf(out);
    }
    __syncthreads();
    if (tid < 128) {
        int ln3 = tid >> 5, o3 = tid & 31;
        int nn = blockIdx.x * 4 + ln3;
        float a0 = 0.f, a1 = 0.f, ar = 0.f;
#pragma unroll 8
        for (int i = 0; i < 64; i++) {
            float xv = sx[ln3][i];
            a0 += xv * g_Wl3[i * 32 + o3];
            a1 += xv * g_Wl3[64 * 32 + i * 32 + o3];
            ar += xv * root3[i * 32 + o3];
        }
        g_hrA[nn * 32 + o3] = a0;
        g_hrA[NN * 32 + nn * 32 + o3] = a1;
        g_rootout3[nn * 32 + o3] = ar + rbias3[o3];
    }
}

// ---------------- kernel 7: agg3 + GAT h GEMM + asv/adv, fused ----------------
__global__ void agg3_gath_kernel(const float* __restrict__ gw,
                                 const float* __restrict__ as, const float* __restrict__ ad) {
    __shared__ __align__(16) float sx[16][32];
    __shared__ float s_as[16], s_ad[16];
    int tid = threadIdx.x;  // 512
    int node0 = blockIdx.x * 16;
    int w = tid >> 5, lane = tid & 31;
    // phase 0: agg3, warp per node
    {
        int node = node0 + w;
        int beg = g_rowptr[node], end = g_rowptr[node + 1];
        float a0 = 0.f, a1 = 0.f, c0 = 0.f, c1 = 0.f;
        int k = beg;
        for (; k + 4 <= end; k += 4) {
            int v0 = g_es[k], v1 = g_es[k + 1], v2 = g_es[k + 2], v3 = g_es[k + 3];
            float f0 = g_hrA[ES_T(v0) * (NN * 32) + ES_S(v0) * 32 + lane];
            float f1 = g_hrA[ES_T(v1) * (NN * 32) + ES_S(v1) * 32 + lane];
            float f2 = g_hrA[ES_T(v2) * (NN * 32) + ES_S(v2) * 32 + lane];
            float f3 = g_hrA[ES_T(v3) * (NN * 32) + ES_S(v3) * 32 + lane];
            if (ES_T(v0)) { a1 += f0; c1 += 1.f; } else { a0 += f0; c0 += 1.f; }
            if (ES_T(v1)) { a1 += f1; c1 += 1.f; } else { a0 += f1; c0 += 1.f; }
            if (ES_T(v2)) { a1 += f2; c1 += 1.f; } else { a0 += f2; c0 += 1.f; }
            if (ES_T(v3)) { a1 += f3; c1 += 1.f; } else { a0 += f3; c0 += 1.f; }
        }
        for (; k < end; k++) {
            int v = g_es[k];
            float f = g_hrA[ES_T(v) * (NN * 32) + ES_S(v) * 32 + lane];
            if (ES_T(v)) { a1 += f; c1 += 1.f; } else { a0 += f; c0 += 1.f; }
        }
        float out = g_rootout3[node * 32 + lane] + a0 / fmaxf(c0, 1.f) + a1 / fmaxf(c1, 1.f);
        sx[w][lane] = tanhf(out);
    }
    if (tid < 16) { s_as[tid] = 0.f; s_ad[tid] = 0.f; }
    __syncthreads();
    // phase 1: GEMM 32 -> 512 with fused attention-logit dots
    int cg = tid & 127;
    int ng = tid >> 7;
    int col4 = cg * 4;
    int nbase = ng * 4;
    float acc[4][4];
#pragma unroll
    for (int a = 0; a < 4; a++)
#pragma unroll
        for (int b = 0; b < 4; b++) acc[a][b] = 0.f;
#pragma unroll 8
    for (int i = 0; i < 32; i++) {
        float4 wv = *(const float4*)(gw + i * 512 + col4);
        float x0 = sx[nbase + 0][i], x1 = sx[nbase + 1][i];
        float x2 = sx[nbase + 2][i], x3 = sx[nbase + 3][i];
        acc[0][0] += x0 * wv.x; acc[0][1] += x0 * wv.y; acc[0][2] += x0 * wv.z; acc[0][3] += x0 * wv.w;
        acc[1][0] += x1 * wv.x; acc[1][1] += x1 * wv.y; acc[1][2] += x1 * wv.z; acc[1][3] += x1 * wv.w;
        acc[2][0] += x2 * wv.x; acc[2][1] += x2 * wv.y; acc[2][2] += x2 * wv.z; acc[2][3] += x2 * wv.w;
        acc[3][0] += x3 * wv.x; acc[3][1] += x3 * wv.y; acc[3][2] += x3 * wv.z; acc[3][3] += x3 * wv.w;
    }
#pragma unroll
    for (int a = 0; a < 4; a++) {
        int nn = node0 + nbase + a;
        float4 o = make_float4(acc[a][0], acc[a][1], acc[a][2], acc[a][3]);
        *(float4*)(g_h + (size_t)nn * 512 + col4) = o;
    }
    float4 av = *(const float4*)(as + col4);
    float4 dv = *(const float4*)(ad + col4);
#pragma unroll
    for (int a = 0; a < 4; a++) {
        float ps = acc[a][0] * av.x + acc[a][1] * av.y + acc[a][2] * av.z + acc[a][3] * av.w;
        float pd = acc[a][0] * dv.x + acc[a][1] * dv.y + acc[a][2] * dv.z + acc[a][3] * dv.w;
#pragma unroll
        for (int off = 16; off; off >>= 1) {
            ps += __shfl_down_sync(0xffffffffu, ps, off);
            pd += __shfl_down_sync(0xffffffffu, pd, off);
        }
        if (lane == 0) {
            atomicAdd(&s_as[nbase + a], ps);
            atomicAdd(&s_ad[nbase + a], pd);
        }
    }
    __syncthreads();
    if (tid < 16) {
        int nn = node0 + tid;
        g_asv[nn] = s_as[tid];
        g_adv[nn] = s_ad[tid];
    }
}

// ---------------- kernel 8: GAT softmax-agg + edge-MLP node projection, fused ----------------
__global__ void gatagg_ptpb_kernel(const float* __restrict__ gbias,
                                   const float* __restrict__ w1, const float* __restrict__ b1) {
    __shared__ __align__(16) float sx[16][512];
    __shared__ float sex[2][64];
    __shared__ int ssrc[2][64];
    int tid = threadIdx.x;
    int node0 = blockIdx.x * 16;
    int g = tid >> 7;
    int gtid = tid & 127;
    const float4* h4 = (const float4*)g_h;
    float4 gb4 = ((const float4*)gbias)[gtid];
    for (int k = 0; k < 8; k++) {
        int n = node0 + g * 8 + k;
        int beg = g_rowptr[n], deg = g_rowptr[n + 1] - beg;
        float advn = g_adv[n];
        float exself = expf(lrelu(g_asv[n] + advn));
        float4 hs = h4[(size_t)n * 128 + gtid];
        float ax = exself * hs.x, ay = exself * hs.y, az = exself * hs.z, aw = exself * hs.w;
        float dsum = exself;
        for (int base = 0; base < deg; base += 64) {
            int cnt = min(64, deg - base);
            if (gtid < cnt) {
                int v = g_es[beg + base + gtid];
                int s = ES_S(v);
                ssrc[g][gtid] = s;
                sex[g][gtid] = expf(lrelu(g_asv[s] + advn));
            }
            asm volatile("bar.sync %0, %1;" :: "r"(g + 1), "r"(128) : "memory");
            for (int j = 0; j < cnt; j++) {
                float exv = sex[g][j];
                float4 hv = h4[(size_t)ssrc[g][j] * 128 + gtid];
                ax += exv * hv.x; ay += exv * hv.y; az += exv * hv.z; aw += exv * hv.w;
                dsum += exv;
            }
            asm volatile("bar.sync %0, %1;" :: "r"(g + 1), "r"(128) : "memory");
        }
        float inv = 1.f / fmaxf(dsum, 1e-16f);
        float4 o = make_float4(fmaxf(ax * inv + gb4.x, 0.f), fmaxf(ay * inv + gb4.y, 0.f),
                               fmaxf(az * inv + gb4.z, 0.f), fmaxf(aw * inv + gb4.w, 0.f));
        ((float4*)sx[g * 8 + k])[gtid] = o;
    }
    __syncthreads();
    int cg = tid & 63;
    int ng = tid >> 6;
    int half = cg >> 5;
    int col4 = (cg & 31) * 4;
    const float* wp = w1 + (half ? 512 * 128 : 0) + col4;
    int nbase = ng * 4;
    float acc[4][4];
#pragma unroll
    for (int a = 0; a < 4; a++)
#pragma unroll
        for (int b = 0; b < 4; b++) acc[a][b] = 0.f;
#pragma unroll 4
    for (int i = 0; i < 512; i++) {
        float4 wv = *(const float4*)(wp + i * 128);
        float x0 = sx[nbase + 0][i], x1 = sx[nbase + 1][i];
        float x2 = sx[nbase + 2][i], x3 = sx[nbase + 3][i];
        acc[0][0] += x0 * wv.x; acc[0][1] += x0 * wv.y; acc[0][2] += x0 * wv.z; acc[0][3] += x0 * wv.w;
        acc[1][0] += x1 * wv.x; acc[1][1] += x1 * wv.y; acc[1][2] += x1 * wv.z; acc[1][3] += x1 * wv.w;
        acc[2][0] += x2 * wv.x; acc[2][1] += x2 * wv.y; acc[2][2] += x2 * wv.z; acc[2][3] += x2 * wv.w;
        acc[3][0] += x3 * wv.x; acc[3][1] += x3 * wv.y; acc[3][2] += x3 * wv.z; acc[3][3] += x3 * wv.w;
    }
    float4 bb = half ? make_float4(0.f, 0.f, 0.f, 0.f) : *(const float4*)(b1 + col4);
    float* obase = half ? g_pb : g_pt;
#pragma unroll
    for (int a = 0; a < 4; a++) {
        int nn = node0 + nbase + a;
        float4 o = make_float4(acc[a][0] + bb.x, acc[a][1] + bb.y,
                               acc[a][2] + bb.z, acc[a][3] + bb.w);
        *(float4*)(obase + (size_t)nn * 128 + col4) = o;
    }
}

// ---------------- kernel 9: per-edge output, CSR order (pb[dst] loaded once/warp) ----------------
__global__ void edge_out_kernel(const float* __restrict__ w2, const float* __restrict__ b2,
                                float* __restrict__ out) {
    int tid = threadIdx.x, w = tid >> 5, lane = tid & 31;
    int node = blockIdx.x * 8 + w;
    int beg = g_rowptr[node], end = g_rowptr[node + 1];
    if (beg == end) return;
    const float4* pt4 = (const float4*)g_pt;
    float4 pbv = ((const float4*)g_pb)[(size_t)node * 32 + lane];
    float4 wv = ((const float4*)w2)[lane];
    float bias = b2[0];
    int k = beg;
    for (; k + 2 <= end; k += 2) {
        int v0 = g_es[k], v1 = g_es[k + 1];
        float4 a0 = pt4[(size_t)ES_S(v0) * 32 + lane];
        float4 a1 = pt4[(size_t)ES_S(v1) * 32 + lane];
        float r0 = fmaxf(a0.x + pbv.x, 0.f) * wv.x + fmaxf(a0.y + pbv.y, 0.f) * wv.y
                 + fmaxf(a0.z + pbv.z, 0.f) * wv.z + fmaxf(a0.w + pbv.w, 0.f) * wv.w;
        float r1 = fmaxf(a1.x + pbv.x, 0.f) * wv.x + fmaxf(a1.y + pbv.y, 0.f) * wv.y
                 + fmaxf(a1.z + pbv.z, 0.f) * wv.z + fmaxf(a1.w + pbv.w, 0.f) * wv.w;
#pragma unroll
        for (int off = 16; off; off >>= 1) {
            r0 += __shfl_down_sync(0xffffffffu, r0, off);
            r1 += __shfl_down_sync(0xffffffffu, r1, off);
        }
        if (lane == 0) {
            out[ES_E(v0)] = 1.f / (1.f + expf(-(r0 + bias)));
            out[ES_E(v1)] = 1.f / (1.f + expf(-(r1 + bias)));
        }
    }
    if (k < end) {
        int v = g_es[k];
        float4 a = pt4[(size_t)ES_S(v) * 32 + lane];
        float r = fmaxf(a.x + pbv.x, 0.f) * wv.x + fmaxf(a.y + pbv.y, 0.f) * wv.y
                + fmaxf(a.z + pbv.z, 0.f) * wv.z + fmaxf(a.w + pbv.w, 0.f) * wv.w;
#pragma unroll
        for (int off = 16; off; off >>= 1) r += __shfl_down_sync(0xffffffffu, r, off);
        if (lane == 0) out[ES_E(v)] = 1.f / (1.f + expf(-(r + bias)));
    }
}

// ---------------- launch ----------------
extern "C" void kernel_launch(void* const* d_in, const int* in_sizes, int n_in,
                              void* d_out, int out_size) {
    int off, iE, iT;
    if (in_sizes[0] == 2 * EE) { off = 2; iE = 0; iT = 1; }
    else                       { off = 0; iE = 24; iT = 25; }
    const int* ei = (const int*)d_in[iE];
    const int* et = (const int*)d_in[iT];
    const int* src = ei;
    const int* dst = ei + EE;
    const float* basis0 = (const float*)d_in[off + 0];
    const float* comp0  = (const float*)d_in[off + 1];
    const float* root0  = (const float*)d_in[off + 2];
    const float* rbias0 = (const float*)d_in[off + 3];
    const float* basis1 = (const float*)d_in[off + 4];
    const float* comp1  = (const float*)d_in[off + 5];
    const float* root1  = (const float*)d_in[off + 6];
    const float* rbias1 = (const float*)d_in[off + 7];
    const float* basis2 = (const float*)d_in[off + 8];
    const float* comp2  = (const float*)d_in[off + 9];
    const float* root2  = (const float*)d_in[off + 10];
    const float* rbias2 = (const float*)d_in[off + 11];
    const float* basis3 = (const float*)d_in[off + 12];
    const float* comp3  = (const float*)d_in[off + 13];
    const float* root3  = (const float*)d_in[off + 14];
    const float* rbias3 = (const float*)d_in[off + 15];
    const float* gw  = (const float*)d_in[off + 16];
    const float* gas = (const float*)d_in[off + 17];
    const float* gad = (const float*)d_in[off + 18];
    const float* gb  = (const float*)d_in[off + 19];
    const float* w1  = (const float*)d_in[off + 20];
    const float* b1  = (const float*)d_in[off + 21];
    const float* w2  = (const float*)d_in[off + 22];
    const float* b2  = (const float*)d_in[off + 23];
    float* out = (float*)d_out;

    pre_count_kernel<<<PRE_BLOCKS + CNT_BLOCKS, 256>>>(basis0, comp0, basis1, comp1,
                                                       basis2, comp2, basis3, comp3, dst);
    scan_kernel<<<1, 1024>>>();
    scatter_kernel<<<CNT_BLOCKS, 256>>>(src, dst, et);

    l0d1_kernel<<<NN / 8, 256>>>(root0, rbias0, root1, rbias1);
    a1d2_kernel<<<NN / 4, 256>>>(root2, rbias2);
    a2d3_kernel<<<NN / 4, 256>>>(root3, rbias3);

    agg3_gath_kernel<<<NN / 16, 512>>>(gw, gas, gad);
    gatagg_ptpb_kernel<<<NN / 16, 256>>>(gb, w1, b1);
    edge_out_kernel<<<NN / 8, 256>>>(w2, b2, out);
}